// round 17
// baseline (speedup 1.0000x reference)
#include <cuda_runtime.h>
#include <cuda_fp16.h>
#include <cstddef>

#define NB 2
#define NC 128
#define TWOC 256
#define NE 60000
#define ETILES (NE / 32)                             // 1875
#define TRB (2 * NB * ETILES)                        // 7500 full-channel tiles
#define W_BLOCKS 7                                   // 6 fold + 1 bias
#define GROUPS4   (NB * NE / 4)                      // 30000 4-edge groups

// Transposed inputs in fp16, tensor-interleaved: [b][e][tensor][c] (512B/edge)
__device__ __half g_xti[(size_t)NB * NE * TWOC];
// Effective fused weights: [branch][c][s*3+k] padded to 16
__device__ float g_V[2][NC][16];
__device__ float g_cb[3];
// Precontracted self contribution (float4 {k0,k1,k2,0}); bias in tensor 0
__device__ float4 g_P0f[2][(size_t)NB * NE];
// ordering flags (self-resetting each launch for graph-replay determinism)
__device__ int g_doneV = 0;
__device__ int g_doneT = 0;
__device__ volatile int g_vflag = 0;

// ---------------------------------------------------------------------------
// Kernel 1 (fused):
//  blocks [0,6):   coalesced weight fold, one block per (tensor,k)
//  block 6:        bias fold
//  blocks [7, +TRB): transpose a full-channel (128c x 32e) tile of one
//    (tensor,b); after flag, compute its P0 float4 slice from smem.
// ---------------------------------------------------------------------------
__global__ void __launch_bounds__(256)
prep_kernel(const float* __restrict__ x0, const float* __restrict__ x1,
    const float* __restrict__ Wa_local, const float* __restrict__ ba_local,
    const float* __restrict__ Wb_local, const float* __restrict__ bb_local,
    const float* __restrict__ Wa_tri,   const float* __restrict__ ba_tri,
    const float* __restrict__ Wb_tri,   const float* __restrict__ bb_tri,
    const float* __restrict__ Wa_fuse,  const float* __restrict__ ba_fuse,
    const float* __restrict__ Wb_fuse,  const float* __restrict__ bb_fuse)
{
    const int lane = threadIdx.x & 31;

    if (blockIdx.x < W_BLOCKS) {
        if (blockIdx.x < 6) {
            // ---- coalesced fold for (t, k) ----
            const int t = blockIdx.x / 3;
            const int k = blockIdx.x % 3;
            const float* Wf = t ? Wb_fuse  : Wa_fuse;
            const float* Wt = t ? Wb_tri   : Wa_tri;
            const float* Wl = t ? Wb_local : Wa_local;

            __shared__ float wf1[NC], wf2[NC], loc[NC];
            if (threadIdx.x < NC)
                wf1[threadIdx.x] = Wf[k * 2 * NC + threadIdx.x];
            else
                wf2[threadIdx.x - NC] = Wf[k * 2 * NC + threadIdx.x];
            __syncthreads();

            // tri part: thread owns i, i+256, (i+512 if i<128); i=(c*5+s)
            float a0 = 0.f, a1 = 0.f, a2 = 0.f;
            const int i0 = threadIdx.x, i1 = threadIdx.x + 256,
                      i2 = threadIdx.x + 512;
            for (int o = 0; o < NC; o++) {
                const float w = wf2[o];
                const float* row = Wt + (size_t)o * (NC * 5);
                a0 = fmaf(w, row[i0], a0);
                a1 = fmaf(w, row[i1], a1);
                if (threadIdx.x < 128) a2 = fmaf(w, row[i2], a2);
            }
            // local part (s==0): loc[c] = sum_o wf1[o]*Wl[o][c]
            if (threadIdx.x < NC) {
                float a = 0.f;
                for (int o = 0; o < NC; o++)
                    a = fmaf(wf1[o], Wl[o * NC + threadIdx.x], a);
                loc[threadIdx.x] = a;
            }
            __syncthreads();

#define WRITE_V(iv, av)                                                  \
            {                                                            \
                const int c = (iv) / 5, s = (iv) - 5 * c;                \
                float v = (av);                                          \
                if (s == 0) v += loc[c];                                 \
                g_V[t][c][s * 3 + k] = v;                                \
            }
            WRITE_V(i0, a0)
            WRITE_V(i1, a1)
            if (threadIdx.x < 128) WRITE_V(i2, a2)
#undef WRITE_V
            if (k == 0 && threadIdx.x < 128)
                g_V[t][threadIdx.x][15] = 0.f;
        } else {
            // ---- bias fold: warps 0-2, k = warp id ----
            const int w = threadIdx.x >> 5;
            if (w < 3) {
                float acc = 0.f;
#pragma unroll
                for (int j = 0; j < 4; j++) {
                    int o = lane + 32 * j;
                    acc = fmaf(Wa_fuse[w * 2 * NC + o],      ba_local[o], acc);
                    acc = fmaf(Wa_fuse[w * 2 * NC + NC + o], ba_tri[o],   acc);
                    acc = fmaf(Wb_fuse[w * 2 * NC + o],      bb_local[o], acc);
                    acc = fmaf(Wb_fuse[w * 2 * NC + NC + o], bb_tri[o],   acc);
                }
#pragma unroll
                for (int off = 16; off; off >>= 1)
                    acc += __shfl_xor_sync(0xffffffffu, acc, off);
                if (lane == 0)
                    g_cb[w] = acc + ba_fuse[w] + bb_fuse[w];
            }
        }

        __syncthreads();
        if (threadIdx.x == 0) {
            __threadfence();
            int old = atomicAdd(&g_doneV, 1);
            if (old == W_BLOCKS - 1) {
                __threadfence();
                g_vflag = 1;
            }
        }
        return;
    }

    // ---- full-channel transpose tile + P0 float4 slice ----
    __shared__ __half tile[32][130];          // [edge][channel], stride 130
    __shared__ float  psum[8][32][3];         // [part][edge][k]
    __shared__ float  p0s[32][4];
    __shared__ float  Vs[NC][3];

    int bx = blockIdx.x - W_BLOCKS;
    const int eb = bx % ETILES;  bx /= ETILES;
    const int b  = bx & 1;
    const int tensor = bx >> 1;
    const float* __restrict__ src = tensor ? x1 : x0;
    const int e0 = eb * 32;
    const int tx = threadIdx.x & 31;
    const int ty = threadIdx.x >> 5;

    // load 128 channels x 32 edges, fp32 -> fp16 smem
#pragma unroll
    for (int i = 0; i < 16; i++) {
        int c = ty + 8 * i;
        tile[tx][c] = __float2half_rn(
            src[((size_t)b * NC + c) * NE + e0 + tx]);
    }
    __syncthreads();

    // store to interleaved xti: warp ty handles edges ty*4..ty*4+3
    {
        const half2* t2 = reinterpret_cast<const half2*>(&tile[0][0]);
#pragma unroll
        for (int it = 0; it < 4; it++) {
            int e = ty * 4 + it;
            unsigned v0 = *reinterpret_cast<const unsigned*>(&t2[e * 65 + tx]);
            unsigned v1 = *reinterpret_cast<const unsigned*>(&t2[e * 65 + 32 + tx]);
            unsigned* dst = reinterpret_cast<unsigned*>(
                g_xti + ((size_t)(b * NE + e0 + e)) * TWOC + tensor * NC);
            dst[tx]      = v0;
            dst[32 + tx] = v1;
        }
    }

    // wait for weights to be globally visible
    if (threadIdx.x == 0) {
        while (g_vflag == 0) __nanosleep(128);
    }
    __syncthreads();

    // stage V slice (s=0)
    for (int i = threadIdx.x; i < NC * 3; i += 256)
        Vs[i / 3][i % 3] = g_V[tensor][i / 3][i % 3];
    __syncthreads();

    // partial dots: thread (tx,ty) -> edge tx, channels ty*16..ty*16+15
    {
        const half2* t2 = reinterpret_cast<const half2*>(&tile[0][0]);
        float a0 = 0.f, a1 = 0.f, a2 = 0.f;
#pragma unroll
        for (int j = 0; j < 8; j++) {
            float2 h = __half22float2(t2[tx * 65 + ty * 8 + j]);
            const int c = ty * 16 + 2 * j;
            a0 = fmaf(Vs[c][0], h.x, a0); a0 = fmaf(Vs[c + 1][0], h.y, a0);
            a1 = fmaf(Vs[c][1], h.x, a1); a1 = fmaf(Vs[c + 1][1], h.y, a1);
            a2 = fmaf(Vs[c][2], h.x, a2); a2 = fmaf(Vs[c + 1][2], h.y, a2);
        }
        psum[ty][tx][0] = a0;
        psum[ty][tx][1] = a1;
        psum[ty][tx][2] = a2;
    }
    __syncthreads();

    // reduce 8 parts; warps 0-2 (k=ty), lane tx = edge
    if (ty < 3) {
        float acc = 0.f;
#pragma unroll
        for (int p = 0; p < 8; p++)
            acc += psum[p][tx][ty];
        p0s[tx][ty] = acc;
    }
    __syncthreads();

    // warp 0: pack float4 (+bias on tensor 0) and store coalesced
    if (ty == 0) {
        float4 v;
        v.x = p0s[tx][0];
        v.y = p0s[tx][1];
        v.z = p0s[tx][2];
        v.w = 0.f;
        if (tensor == 0) {
            v.x += g_cb[0];
            v.y += g_cb[1];
            v.z += g_cb[2];
        }
        g_P0f[tensor][(size_t)b * NE + e0 + tx] = v;
    }

    // self-resetting completion counter (for graph replays)
    __syncthreads();
    if (threadIdx.x == 0) {
        int old = atomicAdd(&g_doneT, 1);
        if (old == TRB - 1) {
            g_doneV = 0;
            g_doneT = 0;
            __threadfence();
            g_vflag = 0;
        }
    }
}

// ---------------------------------------------------------------------------
// Kernel 2: main gather + fused dot. One warp per 4 edges; per edge only the
// 4 NEIGHBOR rows are gathered; self contribution (+bias) folded in from the
// per-tensor float4 P0 planes. Lane 0-15 -> tensor0, lane 16-31 -> tensor1.
// ---------------------------------------------------------------------------
__device__ __forceinline__ __half2 u2h(const unsigned& u)
{
    return *reinterpret_cast<const __half2*>(&u);
}

__device__ __forceinline__ void edge_dot(
    const uint4 r1, const uint4 r2, const uint4 r3, const uint4 r4,
    const __half2 Vp[4][12], float* __restrict__ res)
{
    const __half2 z = __float2half2_rn(0.f);
    __half2 A0 = z, A1 = z, A2 = z, B0 = z, B1 = z, B2 = z;

#define DO_SLOT(j, X1, X2, X3, X4, P0, P1, P2)                            \
    {                                                                     \
        __half2 n1 = u2h(X1), n2 = u2h(X2), n3 = u2h(X3), n4 = u2h(X4);   \
        __half2 G1 = __hadd2(n1, n3), G2 = __hadd2(n2, n4);               \
        __half2 G3 = __habs2(__hsub2(n1, n3));                            \
        __half2 G4 = __habs2(__hsub2(n2, n4));                            \
        P0 = __hfma2(Vp[j][0],  G1, P0);                                  \
        P1 = __hfma2(Vp[j][1],  G1, P1);                                  \
        P2 = __hfma2(Vp[j][2],  G1, P2);                                  \
        P0 = __hfma2(Vp[j][3],  G2, P0);                                  \
        P1 = __hfma2(Vp[j][4],  G2, P1);                                  \
        P2 = __hfma2(Vp[j][5],  G2, P2);                                  \
        P0 = __hfma2(Vp[j][6],  G3, P0);                                  \
        P1 = __hfma2(Vp[j][7],  G3, P1);                                  \
        P2 = __hfma2(Vp[j][8],  G3, P2);                                  \
        P0 = __hfma2(Vp[j][9],  G4, P0);                                  \
        P1 = __hfma2(Vp[j][10], G4, P1);                                  \
        P2 = __hfma2(Vp[j][11], G4, P2);                                  \
    }

    DO_SLOT(0, r1.x, r2.x, r3.x, r4.x, A0, A1, A2)
    DO_SLOT(1, r1.y, r2.y, r3.y, r4.y, A0, A1, A2)
    DO_SLOT(2, r1.z, r2.z, r3.z, r4.z, B0, B1, B2)
    DO_SLOT(3, r1.w, r2.w, r3.w, r4.w, B0, B1, B2)
#undef DO_SLOT

    float2 a0 = __half22float2(A0), b0 = __half22float2(B0);
    float2 a1 = __half22float2(A1), b1 = __half22float2(B1);
    float2 a2 = __half22float2(A2), b2 = __half22float2(B2);
    res[0] = (a0.x + a0.y) + (b0.x + b0.y);
    res[1] = (a1.x + a1.y) + (b1.x + b1.y);
    res[2] = (a2.x + a2.y) + (b2.x + b2.y);
}

// one PAIR of edges: 8 batched LDG.128 (neighbor rows only) -> res[0..5]
__device__ __forceinline__ void do_pair(
    const __half* __restrict__ base,
    const int4 gi0, const int4 gi1,
    const __half2 Vp[4][12], float* __restrict__ res)
{
    uint4 a1 = *reinterpret_cast<const uint4*>(base + (size_t)gi0.x * TWOC);
    uint4 a2 = *reinterpret_cast<const uint4*>(base + (size_t)gi0.y * TWOC);
    uint4 a3 = *reinterpret_cast<const uint4*>(base + (size_t)gi0.z * TWOC);
    uint4 a4 = *reinterpret_cast<const uint4*>(base + (size_t)gi0.w * TWOC);
    uint4 c1 = *reinterpret_cast<const uint4*>(base + (size_t)gi1.x * TWOC);
    uint4 c2 = *reinterpret_cast<const uint4*>(base + (size_t)gi1.y * TWOC);
    uint4 c3 = *reinterpret_cast<const uint4*>(base + (size_t)gi1.z * TWOC);
    uint4 c4 = *reinterpret_cast<const uint4*>(base + (size_t)gi1.w * TWOC);

    edge_dot(a1, a2, a3, a4, Vp, res);
    edge_dot(c1, c2, c3, c4, Vp, res + 3);
}

__global__ void __launch_bounds__(256, 2)
mesh_main_kernel(const int* __restrict__ gemm, float* __restrict__ out)
{
    const int lane = threadIdx.x & 31;
    const int gw   = blockIdx.x * 8 + (threadIdx.x >> 5);
    const int W    = gridDim.x * 8;

    const int lt = lane >> 4;              // tensor
    const int lc = (lane & 15) * 8;        // channel base (8 channels)

    // weights for s=1..4 only: 48 half2 regs
    __half2 Vp[4][12];
#pragma unroll
    for (int j = 0; j < 4; j++) {
        const float* r0 = g_V[lt][lc + 2 * j];
        const float* r1 = g_V[lt][lc + 2 * j + 1];
#pragma unroll
        for (int i = 0; i < 12; i++)
            Vp[j][i] = __floats2half2_rn(r0[3 + i], r1[3 + i]);
    }

    const float4* __restrict__ p0f = g_P0f[lt];
    const int4*   __restrict__ gi4 = reinterpret_cast<const int4*>(gemm);

    int g = gw;
    if (g >= GROUPS4) return;

    int e0 = 4 * g;
    int b  = (e0 >= NE) ? 1 : 0;
    int eb = e0 - b * NE;
    int4 gA = gi4[(size_t)b * NE + eb];
    int4 gB = gi4[(size_t)b * NE + eb + 1];

    while (g < GROUPS4) {
        const int4 gC = gi4[(size_t)b * NE + eb + 2];
        const int4 gD = gi4[(size_t)b * NE + eb + 3];

        const int gn  = g + W;
        const int gnc = (gn < GROUPS4) ? gn : gw;
        const int e0n = 4 * gnc;
        const int bn  = (e0n >= NE) ? 1 : 0;
        const int ebn = e0n - bn * NE;
        const int4 gA_n = gi4[(size_t)bn * NE + ebn];
        const int4 gB_n = gi4[(size_t)bn * NE + ebn + 1];

        const __half* __restrict__ base =
            g_xti + (size_t)b * NE * TWOC + lane * 8;

        // this tensor's precontracted self (+bias) contribution
        const int u = lane & 15;
        float4 p0 = make_float4(0.f, 0.f, 0.f, 0.f);
        if (u < 4)
            p0 = p0f[(size_t)b * NE + eb + u];

        float res[12];
        do_pair(base, gA, gB, Vp, res);
        do_pair(base, gC, gD, Vp, res + 6);

        if (u < 4) {
            res[3 * u + 0] += p0.x;
            res[3 * u + 1] += p0.y;
            res[3 * u + 2] += p0.z;
        }

#pragma unroll
        for (int off = 16; off; off >>= 1)
#pragma unroll
            for (int r = 0; r < 12; r++)
                res[r] += __shfl_xor_sync(0xffffffffu, res[r], off);

        if (lane < 12) {
            const int uu = lane / 3;
            const int k  = lane - 3 * uu;
            out[((size_t)b * 3 + k) * NE + eb + uu] = res[lane];
        }

        g  = gn;
        b  = bn;
        eb = ebn;
        gA = gA_n;
        gB = gB_n;
    }
}

// ---------------------------------------------------------------------------
extern "C" void kernel_launch(void* const* d_in, const int* in_sizes, int n_in,
                              void* d_out, int out_size)
{
    const float* x_0      = (const float*)d_in[0];
    const float* x_1      = (const float*)d_in[1];
    const int*   gemm     = (const int*)  d_in[2];
    const float* Wa_local = (const float*)d_in[3];
    const float* ba_local = (const float*)d_in[4];
    const float* Wb_local = (const float*)d_in[5];
    const float* bb_local = (const float*)d_in[6];
    const float* Wa_tri   = (const float*)d_in[7];
    const float* ba_tri   = (const float*)d_in[8];
    const float* Wb_tri   = (const float*)d_in[9];
    const float* bb_tri   = (const float*)d_in[10];
    const float* Wa_fuse  = (const float*)d_in[11];
    const float* ba_fuse  = (const float*)d_in[12];
    const float* Wb_fuse  = (const float*)d_in[13];
    const float* bb_fuse  = (const float*)d_in[14];
    float* out = (float*)d_out;

    prep_kernel<<<W_BLOCKS + TRB, 256>>>(
        x_0, x_1,
        Wa_local, ba_local, Wb_local, bb_local,
        Wa_tri, ba_tri, Wb_tri, bb_tri,
        Wa_fuse, ba_fuse, Wb_fuse, bb_fuse);

    mesh_main_kernel<<<296, 256>>>(gemm, out);
}